// round 2
// baseline (speedup 1.0000x reference)
#include <cuda_runtime.h>

// ---------------------------------------------------------------------------
// pcqmPostProcess: fused segment-mean (column-split incoming/outgoing) +
// index rebasing. Output layout (float32, flattened tuple order):
//   [ x_new (N_NODES*D) | edge_new (2*E_LAB) | ptr_new (B+1) | batch_vec (N_NODES) ]
// ---------------------------------------------------------------------------

#define MAX_B   2048   // max graphs supported by the 1-block scan
#define MAX_LG  1024   // max line-graph nodes per graph
#define MAX_N   128    // max original nodes per graph

__device__ int g_node_off[MAX_B];   // exclusive cumsum of org_graph_size
__device__ int g_edge_off[MAX_B];   // exclusive cumsum of edge_label_size

// ---------------------------------------------------------------------------
// Kernel 1: block-wide Hillis-Steele scan of org_graph_size and
// edge_label_size; writes ptr_new section of the output and the device
// scratch offsets used by kernel 2. One block, 1024 threads, B <= 2048.
// ---------------------------------------------------------------------------
__global__ void scan_kernel(const int* __restrict__ org,
                            const int* __restrict__ elab,
                            int B, float* __restrict__ out, long long ptr_sec) {
    __shared__ int s0[MAX_B];
    __shared__ int s1[MAX_B];
    int tid = threadIdx.x;                       // blockDim.x == 1024
    for (int i = tid; i < MAX_B; i += 1024) {
        s0[i] = (i < B) ? org[i]  : 0;
        s1[i] = (i < B) ? elab[i] : 0;
    }
    __syncthreads();
    for (int off = 1; off < MAX_B; off <<= 1) {
        int a0[2], a1[2];
#pragma unroll
        for (int j = 0; j < 2; j++) {
            int i = tid + j * 1024;
            a0[j] = (i >= off) ? s0[i - off] : 0;
            a1[j] = (i >= off) ? s1[i - off] : 0;
        }
        __syncthreads();
#pragma unroll
        for (int j = 0; j < 2; j++) {
            int i = tid + j * 1024;
            s0[i] += a0[j];
            s1[i] += a1[j];
        }
        __syncthreads();
    }
    // s0/s1 now hold inclusive cumsums
    for (int i = tid; i < B; i += 1024) {
        g_node_off[i] = s0[i] - org[i];
        g_edge_off[i] = s1[i] - elab[i];
        out[ptr_sec + 1 + i] = (float)s0[i];     // ptr_new[i+1]
    }
    if (tid == 0) out[ptr_sec] = 0.0f;           // ptr_new[0]
}

// ---------------------------------------------------------------------------
// Kernel 2: one block per graph.
//  Phase A: build per-node bucket lists of contributing line-graph rows
//           (separately for endpoint-0 = outgoing, endpoint-1 = incoming).
//  Phase B: each thread gathers one (node, d..d+VEC) output vector:
//           dims < 2*HDIM take the incoming mean, the rest the outgoing mean.
//  Phase C: batch_vec and rebased labeled edge indices.
// ---------------------------------------------------------------------------
template<int VEC>
__global__ void graph_kernel(const float* __restrict__ x,
                             const int*   __restrict__ lgidx,   // [N_LG, 2]
                             const int*   __restrict__ ptr,     // [B+1]
                             const int*   __restrict__ org,     // [B]
                             const int*   __restrict__ elab,    // [B]
                             const int*   __restrict__ eil,     // [2, E_LAB]
                             float*       __restrict__ out,
                             int D, int HDIM, int E_LAB,
                             long long N_NODES, int B) {
    __shared__ unsigned short lin [MAX_LG];   // bucket list keyed by idx1 (incoming)
    __shared__ unsigned short lout[MAX_LG];   // bucket list keyed by idx0 (outgoing)
    __shared__ unsigned short i0s [MAX_LG];
    __shared__ unsigned short i1s [MAX_LG];
    __shared__ int cin [MAX_N], cou [MAX_N];  // counts
    __shared__ int sin_[MAX_N], sou [MAX_N];  // starts
    __shared__ int pin [MAX_N], pou [MAX_N];  // scatter cursors

    const int g    = blockIdx.x;
    const int tid  = threadIdx.x;
    const int nt   = blockDim.x;
    const int p0   = ptr[0];
    const int lg_base = ptr[g] - p0;
    const int lg_n    = ptr[g + 1] - ptr[g];
    const int npg     = org[g];
    const int nbase   = g_node_off[g];

    // --- Phase A: bucket lists ---
    for (int i = tid; i < npg; i += nt) { cin[i] = 0; cou[i] = 0; }
    __syncthreads();
    for (int i = tid; i < lg_n; i += nt) {
        int2 v = ((const int2*)lgidx)[lg_base + i];
        i0s[i] = (unsigned short)v.x;
        i1s[i] = (unsigned short)v.y;
        atomicAdd(&cou[v.x], 1);
        atomicAdd(&cin[v.y], 1);
    }
    __syncthreads();
    if (tid == 0) {
        int a = 0, b = 0;
        for (int n = 0; n < npg; n++) {
            sin_[n] = a; pin[n] = a; a += cin[n];
            sou [n] = b; pou[n] = b; b += cou[n];
        }
    }
    __syncthreads();
    for (int i = tid; i < lg_n; i += nt) {
        int p = atomicAdd(&pou[i0s[i]], 1); lout[p] = (unsigned short)i;
        int q = atomicAdd(&pin[i1s[i]], 1); lin [q] = (unsigned short)i;
    }
    __syncthreads();

    // --- Phase B: gather-mean into x_new ---
    const int Dv   = D / VEC;
    const int nOut = npg * Dv;
    const int twoH = 2 * HDIM;
    for (int o = tid; o < nOut; o += nt) {
        int n = o / Dv;
        int d = (o - n * Dv) * VEC;
        bool use_in = (d < twoH);
        const unsigned short* lst = use_in ? lin : lout;
        int s = use_in ? sin_[n] : sou[n];
        int c = use_in ? cin [n] : cou[n];
        float acc[VEC];
#pragma unroll
        for (int v = 0; v < VEC; v++) acc[v] = 0.0f;
        for (int k = 0; k < c; k++) {
            const float* p = x + (size_t)(lg_base + lst[s + k]) * D + d;
            if (VEC == 4) {
                float4 val = *(const float4*)p;
                acc[0] += val.x; acc[1] += val.y; acc[2] += val.z; acc[3] += val.w;
            } else {
                acc[0] += *p;
            }
        }
        float inv = (c > 0) ? 1.0f / (float)c : 0.0f;
        float* po = out + (size_t)nbase * D + (size_t)n * D + d;
        if (VEC == 4) {
            float4 r;
            r.x = acc[0] * inv; r.y = acc[1] * inv;
            r.z = acc[2] * inv; r.w = acc[3] * inv;
            *(float4*)po = r;
        } else {
            *po = acc[0] * inv;
        }
    }

    // --- Phase C: batch_vec + rebased edges ---
    const long long edge_sec  = N_NODES * (long long)D;
    const long long ptr_sec   = edge_sec + 2LL * E_LAB;
    const long long batch_sec = ptr_sec + (B + 1);
    for (int n = tid; n < npg; n += nt)
        out[batch_sec + nbase + n] = (float)g;

    const int e_base = g_edge_off[g];
    const int e_n    = elab[g];
    for (int j = tid; j < e_n; j += nt) {
        out[edge_sec + e_base + j]         = (float)(eil[e_base + j]         - lg_base);
        out[edge_sec + E_LAB + e_base + j] = (float)(eil[E_LAB + e_base + j] - lg_base);
    }
}

// ---------------------------------------------------------------------------
extern "C" void kernel_launch(void* const* d_in, const int* in_sizes, int n_in,
                              void* d_out, int out_size) {
    const float* x     = (const float*)d_in[0];
    const int*   lgidx = (const int*)  d_in[1];
    const int*   ptr   = (const int*)  d_in[2];
    const int*   org   = (const int*)  d_in[3];
    const int*   elab  = (const int*)  d_in[4];
    const int*   eil   = (const int*)  d_in[5];
    float*       out   = (float*)d_out;

    const int N_LG  = in_sizes[1] / 2;
    const int D     = in_sizes[0] / N_LG;
    const int B     = in_sizes[3];
    const int E_LAB = in_sizes[5] / 2;
    const int HDIM  = D / 3;
    // out_size = N_NODES*D + 2*E_LAB + (B+1) + N_NODES
    const long long N_NODES =
        ((long long)out_size - 2LL * E_LAB - (B + 1)) / (D + 1);
    const long long ptr_sec = N_NODES * (long long)D + 2LL * E_LAB;

    scan_kernel<<<1, 1024>>>(org, elab, B, out, ptr_sec);

    if ((D % 4 == 0) && ((2 * HDIM) % 4 == 0)) {
        graph_kernel<4><<<B, 512>>>(x, lgidx, ptr, org, elab, eil, out,
                                    D, HDIM, E_LAB, N_NODES, B);
    } else {
        graph_kernel<1><<<B, 512>>>(x, lgidx, ptr, org, elab, eil, out,
                                    D, HDIM, E_LAB, N_NODES, B);
    }
}

// round 4
// speedup vs baseline: 1.2165x; 1.2165x over previous
#include <cuda_runtime.h>

// ---------------------------------------------------------------------------
// pcqmPostProcess: fused segment-mean (column-split incoming/outgoing) +
// index rebasing. Output layout (float32, flattened tuple order):
//   [ x_new (N_NODES*D) | edge_new (2*E_LAB) | ptr_new (B+1) | batch_vec (N_NODES) ]
// ---------------------------------------------------------------------------

#define MAX_B   2048   // max graphs supported by the 1-block scan
#define MAX_LG  1024   // max padded bucket-list length per graph per side
#define MAX_N   128    // max original nodes per graph

__device__ int g_node_off[MAX_B];   // exclusive cumsum of org_graph_size
__device__ int g_edge_off[MAX_B];   // exclusive cumsum of edge_label_size

// ---------------------------------------------------------------------------
// Kernel 1: shfl-based dual scan (org_graph_size, edge_label_size).
// 1024 threads, 2 elements per thread -> B <= 2048. Two barriers total.
// ---------------------------------------------------------------------------
__global__ void scan_kernel(const int* __restrict__ org,
                            const int* __restrict__ elab,
                            int B, float* __restrict__ out, long long ptr_sec) {
    const int tid  = threadIdx.x;
    const int lane = tid & 31;
    const int warp = tid >> 5;
    const int i0 = 2 * tid, i1 = 2 * tid + 1;

    int v0 = (i0 < B) ? org[i0]  : 0;
    int v1 = (i1 < B) ? org[i1]  : 0;
    int e0 = (i0 < B) ? elab[i0] : 0;
    int e1 = (i1 < B) ? elab[i1] : 0;

    int sv = v0 + v1, se = e0 + e1;
#pragma unroll
    for (int off = 1; off < 32; off <<= 1) {
        int t = __shfl_up_sync(0xFFFFFFFFu, sv, off); if (lane >= off) sv += t;
        int u = __shfl_up_sync(0xFFFFFFFFu, se, off); if (lane >= off) se += u;
    }
    __shared__ int wsv[32], wse[32];
    if (lane == 31) { wsv[warp] = sv; wse[warp] = se; }
    __syncthreads();
    if (warp == 0) {
        int a = wsv[lane], b = wse[lane];
#pragma unroll
        for (int off = 1; off < 32; off <<= 1) {
            int t = __shfl_up_sync(0xFFFFFFFFu, a, off); if (lane >= off) a += t;
            int u = __shfl_up_sync(0xFFFFFFFFu, b, off); if (lane >= off) b += u;
        }
        wsv[lane] = a; wse[lane] = b;
    }
    __syncthreads();
    const int basev = (warp > 0) ? wsv[warp - 1] : 0;
    const int basee = (warp > 0) ? wse[warp - 1] : 0;
    const int incl1_v = basev + sv, incl0_v = incl1_v - v1;
    const int incl1_e = basee + se, incl0_e = incl1_e - e1;
    if (i0 < B) {
        g_node_off[i0] = incl0_v - v0;
        g_edge_off[i0] = incl0_e - e0;
        out[ptr_sec + 1 + i0] = (float)incl0_v;
    }
    if (i1 < B) {
        g_node_off[i1] = incl1_v - v1;
        g_edge_off[i1] = incl1_e - e1;
        out[ptr_sec + 1 + i1] = (float)incl1_v;
    }
    if (tid == 0) out[ptr_sec] = 0.0f;
}

// ---------------------------------------------------------------------------
// Kernel 2: one block per graph.
//  Phase A: per-node bucket lists, PADDED to multiples of 4 with 0xFFFF
//           sentinels so Phase B runs a branch-free unroll-4 gather.
//  Phase B: each thread owns one (node, d..d+3) float4 output lane; issues
//           4 independent predicated LDG.128 per loop trip.
//  Phase C: batch_vec and rebased labeled edge indices.
// ---------------------------------------------------------------------------
__global__ void graph_kernel4(const float* __restrict__ x,
                              const int*   __restrict__ lgidx,   // [N_LG, 2]
                              const int*   __restrict__ ptr,     // [B+1]
                              const int*   __restrict__ org,     // [B]
                              const int*   __restrict__ elab,    // [B]
                              const int*   __restrict__ eil,     // [2, E_LAB]
                              float*       __restrict__ out,
                              int D, int HDIM, int E_LAB,
                              long long N_NODES, int B) {
    __shared__ __align__(8) unsigned short lin [MAX_LG];  // keyed by idx1 (incoming)
    __shared__ __align__(8) unsigned short lout[MAX_LG];  // keyed by idx0 (outgoing)
    __shared__ unsigned short i0s [MAX_LG];
    __shared__ unsigned short i1s [MAX_LG];
    __shared__ int cin [MAX_N], cou [MAX_N];  // counts
    __shared__ int sin_[MAX_N], sou [MAX_N];  // padded starts
    __shared__ int pin [MAX_N], pou [MAX_N];  // scatter cursors
    __shared__ int tot_in, tot_ou;            // padded totals

    const int g    = blockIdx.x;
    const int tid  = threadIdx.x;
    const int nt   = blockDim.x;
    const int p0      = ptr[0];
    const int lg_base = ptr[g] - p0;
    const int lg_n    = ptr[g + 1] - ptr[g];
    const int npg     = org[g];
    const int nbase   = g_node_off[g];

    // --- Phase A: counts ---
    for (int i = tid; i < npg; i += nt) { cin[i] = 0; cou[i] = 0; }
    __syncthreads();
    for (int i = tid; i < lg_n; i += nt) {
        int2 v = ((const int2*)lgidx)[lg_base + i];
        i0s[i] = (unsigned short)v.x;
        i1s[i] = (unsigned short)v.y;
        atomicAdd(&cou[v.x], 1);
        atomicAdd(&cin[v.y], 1);
    }
    __syncthreads();
    if (tid == 0) {
        int a = 0, b = 0;
        for (int n = 0; n < npg; n++) {
            sin_[n] = a; pin[n] = a; a += (cin[n] + 3) & ~3;
            sou [n] = b; pou[n] = b; b += (cou[n] + 3) & ~3;
        }
        tot_in = a; tot_ou = b;
    }
    __syncthreads();
    // sentinel-fill padded regions
    const int ti = tot_in, to = tot_ou;
    for (int i = tid; i < ti; i += nt) lin [i] = 0xFFFFu;
    for (int i = tid; i < to; i += nt) lout[i] = 0xFFFFu;
    __syncthreads();
    for (int i = tid; i < lg_n; i += nt) {
        int p = atomicAdd(&pou[i0s[i]], 1); lout[p] = (unsigned short)i;
        int q = atomicAdd(&pin[i1s[i]], 1); lin [q] = (unsigned short)i;
    }
    __syncthreads();

    // --- Phase B: unroll-4 gather-mean into x_new ---
    const int Dv    = D >> 2;               // float4 lanes per row
    const int nOut  = npg * Dv;
    const int twoHv = (2 * HDIM) >> 2;
    const float* xg = x + (size_t)lg_base * D;

    for (int o = tid; o < nOut; o += nt) {
        const int n  = o / Dv;
        const int dv = o - n * Dv;
        const bool use_in = (dv < twoHv);
        const unsigned short* lst = use_in ? lin : lout;
        const int s = use_in ? sin_[n] : sou[n];
        const int c = use_in ? cin [n] : cou[n];
        const int cpad = (c + 3) & ~3;
        const float* xb = xg + (size_t)dv * 4;

        float ax = 0.f, ay = 0.f, az = 0.f, aw = 0.f;
        for (int k = 0; k < cpad; k += 4) {
            ushort4 iv = *reinterpret_cast<const ushort4*>(lst + s + k);
            if (iv.x != 0xFFFFu) {
                float4 v = __ldcs((const float4*)(xb + (size_t)iv.x * D));
                ax += v.x; ay += v.y; az += v.z; aw += v.w;
            }
            if (iv.y != 0xFFFFu) {
                float4 v = __ldcs((const float4*)(xb + (size_t)iv.y * D));
                ax += v.x; ay += v.y; az += v.z; aw += v.w;
            }
            if (iv.z != 0xFFFFu) {
                float4 v = __ldcs((const float4*)(xb + (size_t)iv.z * D));
                ax += v.x; ay += v.y; az += v.z; aw += v.w;
            }
            if (iv.w != 0xFFFFu) {
                float4 v = __ldcs((const float4*)(xb + (size_t)iv.w * D));
                ax += v.x; ay += v.y; az += v.z; aw += v.w;
            }
        }
        const float inv = (c > 0) ? 1.0f / (float)c : 0.0f;
        float4 r;
        r.x = ax * inv; r.y = ay * inv; r.z = az * inv; r.w = aw * inv;
        __stcs((float4*)(out + (size_t)(nbase + n) * D + (size_t)dv * 4), r);
    }

    // --- Phase C: batch_vec + rebased edges ---
    const long long edge_sec  = N_NODES * (long long)D;
    const long long ptr_sec   = edge_sec + 2LL * E_LAB;
    const long long batch_sec = ptr_sec + (B + 1);
    for (int n = tid; n < npg; n += nt)
        out[batch_sec + nbase + n] = (float)g;

    const int e_base = g_edge_off[g];
    const int e_n    = elab[g];
    for (int j = tid; j < e_n; j += nt) {
        out[edge_sec + e_base + j]         = (float)(eil[e_base + j]         - lg_base);
        out[edge_sec + E_LAB + e_base + j] = (float)(eil[E_LAB + e_base + j] - lg_base);
    }
}

// ---------------------------------------------------------------------------
// Scalar fallback (D not divisible by 4) — same structure, unpadded lists.
// ---------------------------------------------------------------------------
__global__ void graph_kernel1(const float* __restrict__ x,
                              const int*   __restrict__ lgidx,
                              const int*   __restrict__ ptr,
                              const int*   __restrict__ org,
                              const int*   __restrict__ elab,
                              const int*   __restrict__ eil,
                              float*       __restrict__ out,
                              int D, int HDIM, int E_LAB,
                              long long N_NODES, int B) {
    __shared__ unsigned short lin [MAX_LG];
    __shared__ unsigned short lout[MAX_LG];
    __shared__ unsigned short i0s [MAX_LG];
    __shared__ unsigned short i1s [MAX_LG];
    __shared__ int cin [MAX_N], cou [MAX_N];
    __shared__ int sin_[MAX_N], sou [MAX_N];
    __shared__ int pin [MAX_N], pou [MAX_N];

    const int g    = blockIdx.x;
    const int tid  = threadIdx.x;
    const int nt   = blockDim.x;
    const int p0      = ptr[0];
    const int lg_base = ptr[g] - p0;
    const int lg_n    = ptr[g + 1] - ptr[g];
    const int npg     = org[g];
    const int nbase   = g_node_off[g];

    for (int i = tid; i < npg; i += nt) { cin[i] = 0; cou[i] = 0; }
    __syncthreads();
    for (int i = tid; i < lg_n; i += nt) {
        int2 v = ((const int2*)lgidx)[lg_base + i];
        i0s[i] = (unsigned short)v.x;
        i1s[i] = (unsigned short)v.y;
        atomicAdd(&cou[v.x], 1);
        atomicAdd(&cin[v.y], 1);
    }
    __syncthreads();
    if (tid == 0) {
        int a = 0, b = 0;
        for (int n = 0; n < npg; n++) {
            sin_[n] = a; pin[n] = a; a += cin[n];
            sou [n] = b; pou[n] = b; b += cou[n];
        }
    }
    __syncthreads();
    for (int i = tid; i < lg_n; i += nt) {
        int p = atomicAdd(&pou[i0s[i]], 1); lout[p] = (unsigned short)i;
        int q = atomicAdd(&pin[i1s[i]], 1); lin [q] = (unsigned short)i;
    }
    __syncthreads();

    const int nOut = npg * D;
    const int twoH = 2 * HDIM;
    for (int o = tid; o < nOut; o += nt) {
        int n = o / D;
        int d = o - n * D;
        bool use_in = (d < twoH);
        const unsigned short* lst = use_in ? lin : lout;
        int s = use_in ? sin_[n] : sou[n];
        int c = use_in ? cin [n] : cou[n];
        float acc = 0.f;
        for (int k = 0; k < c; k++)
            acc += x[(size_t)(lg_base + lst[s + k]) * D + d];
        out[(size_t)(nbase + n) * D + d] = (c > 0) ? acc / (float)c : 0.0f;
    }

    const long long edge_sec  = N_NODES * (long long)D;
    const long long ptr_sec   = edge_sec + 2LL * E_LAB;
    const long long batch_sec = ptr_sec + (B + 1);
    for (int n = tid; n < npg; n += nt)
        out[batch_sec + nbase + n] = (float)g;
    const int e_base = g_edge_off[g];
    const int e_n    = elab[g];
    for (int j = tid; j < e_n; j += nt) {
        out[edge_sec + e_base + j]         = (float)(eil[e_base + j]         - lg_base);
        out[edge_sec + E_LAB + e_base + j] = (float)(eil[E_LAB + e_base + j] - lg_base);
    }
}

// ---------------------------------------------------------------------------
extern "C" void kernel_launch(void* const* d_in, const int* in_sizes, int n_in,
                              void* d_out, int out_size) {
    const float* x     = (const float*)d_in[0];
    const int*   lgidx = (const int*)  d_in[1];
    const int*   ptr   = (const int*)  d_in[2];
    const int*   org   = (const int*)  d_in[3];
    const int*   elab  = (const int*)  d_in[4];
    const int*   eil   = (const int*)  d_in[5];
    float*       out   = (float*)d_out;

    const int N_LG  = in_sizes[1] / 2;
    const int D     = in_sizes[0] / N_LG;
    const int B     = in_sizes[3];
    const int E_LAB = in_sizes[5] / 2;
    const int HDIM  = D / 3;
    // out_size = N_NODES*D + 2*E_LAB + (B+1) + N_NODES
    const long long N_NODES =
        ((long long)out_size - 2LL * E_LAB - (B + 1)) / (D + 1);
    const long long ptr_sec = N_NODES * (long long)D + 2LL * E_LAB;

    scan_kernel<<<1, 1024>>>(org, elab, B, out, ptr_sec);

    if ((D % 4 == 0) && ((2 * HDIM) % 4 == 0)) {
        graph_kernel4<<<B, 512>>>(x, lgidx, ptr, org, elab, eil, out,
                                  D, HDIM, E_LAB, N_NODES, B);
    } else {
        graph_kernel1<<<B, 512>>>(x, lgidx, ptr, org, elab, eil, out,
                                  D, HDIM, E_LAB, N_NODES, B);
    }
}